// round 1
// baseline (speedup 1.0000x reference)
#include <cuda_runtime.h>
#include <math.h>

// Problem-fixed maxima (reference: N=50000, E=800000, dims 256/64/32/3)
#define NMAX 50048
#define EMAX 800000

// Scratch (device globals: no allocation allowed)
__device__ float g_h1pre[NMAX * 64];   // x @ W_enc_gnn
__device__ float g_h1[NMAX * 64];      // relu(agg(h1pre)+b)
__device__ float g_hd[NMAX * 64];      // relu(z@W_dec_fc+b)
__device__ float g_a2[NMAX * 64];      // agg(hd)
__device__ float g_dinv[NMAX];
__device__ int   g_cnt[NMAX];          // in-degree (no self loop)
__device__ int   g_cur[NMAX];
__device__ int   g_off[NMAX + 1];      // CSR offsets
__device__ int   g_esrc[EMAX];         // dst-sorted src ids
__device__ int   g_bsums[128];         // scan partials

// ---------------------------------------------------------------------------
// CSR build + degree normalization
// ---------------------------------------------------------------------------
__global__ void k_init(int n) {
    int i = blockIdx.x * blockDim.x + threadIdx.x;
    if (i < n) { g_cnt[i] = 0; g_cur[i] = 0; }
}

__global__ void k_count(const int* __restrict__ dst, int E) {
    int e = blockIdx.x * blockDim.x + threadIdx.x;
    if (e < E) atomicAdd(&g_cnt[dst[e]], 1);
}

__global__ void k_dinv(int n) {
    int i = blockIdx.x * blockDim.x + threadIdx.x;
    if (i < n) g_dinv[i] = rsqrtf(1.0f + (float)g_cnt[i]);  // +1 self loop
}

// scan phase 1: per-1024-block sums
__global__ void k_scan_bsum(int n) {
    __shared__ int s[1024];
    int i = blockIdx.x * 1024 + threadIdx.x;
    s[threadIdx.x] = (i < n) ? g_cnt[i] : 0;
    __syncthreads();
    for (int st = 512; st > 0; st >>= 1) {
        if (threadIdx.x < st) s[threadIdx.x] += s[threadIdx.x + st];
        __syncthreads();
    }
    if (threadIdx.x == 0) g_bsums[blockIdx.x] = s[0];
}

// scan phase 2: exclusive scan of block sums (single block, nb <= 1024)
__global__ void k_scan_sums(int nb) {
    __shared__ int s[1024];
    int v = (threadIdx.x < nb) ? g_bsums[threadIdx.x] : 0;
    s[threadIdx.x] = v;
    __syncthreads();
    for (int st = 1; st < 1024; st <<= 1) {
        int t = (threadIdx.x >= st) ? s[threadIdx.x - st] : 0;
        __syncthreads();
        s[threadIdx.x] += t;
        __syncthreads();
    }
    if (threadIdx.x < nb) g_bsums[threadIdx.x] = s[threadIdx.x] - v;  // exclusive
}

// scan phase 3: exclusive offsets
__global__ void k_scan_final(int n, int E) {
    __shared__ int s[1024];
    int i = blockIdx.x * 1024 + threadIdx.x;
    int v = (i < n) ? g_cnt[i] : 0;
    s[threadIdx.x] = v;
    __syncthreads();
    for (int st = 1; st < 1024; st <<= 1) {
        int t = (threadIdx.x >= st) ? s[threadIdx.x - st] : 0;
        __syncthreads();
        s[threadIdx.x] += t;
        __syncthreads();
    }
    if (i < n) g_off[i] = g_bsums[blockIdx.x] + s[threadIdx.x] - v;
    if (i == 0) g_off[n] = E;
}

__global__ void k_fill(const int* __restrict__ src, const int* __restrict__ dst, int E) {
    int e = blockIdx.x * blockDim.x + threadIdx.x;
    if (e < E) {
        int d = dst[e];
        int pos = g_off[d] + atomicAdd(&g_cur[d], 1);
        g_esrc[pos] = src[e];
    }
}

// ---------------------------------------------------------------------------
// GEMM: [M,256] @ [256,64] -> [M,64]   (h1pre = x @ W_enc_gnn)
// ---------------------------------------------------------------------------
__global__ void k_gemm_256_64(const float* __restrict__ A,
                              const float* __restrict__ W,
                              float* __restrict__ C, int M) {
    __shared__ float As[64][65];
    __shared__ float Ws[64][65];
    int tid = threadIdx.x;               // 256 threads
    int tr = tid >> 4, tc = tid & 15;    // 16x16, 4x4 micro-tile each
    int rowBase = blockIdx.x * 64;
    float acc[4][4] = {};
    for (int k0 = 0; k0 < 256; k0 += 64) {
        for (int i = tid; i < 64 * 64; i += 256) {
            int r = i >> 6, c = i & 63;
            int gr = rowBase + r;
            As[r][c] = (gr < M) ? A[gr * 256 + k0 + c] : 0.0f;
            Ws[r][c] = W[(k0 + r) * 64 + c];
        }
        __syncthreads();
#pragma unroll
        for (int k = 0; k < 64; k++) {
            float a[4], b[4];
#pragma unroll
            for (int i = 0; i < 4; i++) a[i] = As[tr * 4 + i][k];
#pragma unroll
            for (int j = 0; j < 4; j++) b[j] = Ws[k][tc * 4 + j];
#pragma unroll
            for (int i = 0; i < 4; i++)
#pragma unroll
                for (int j = 0; j < 4; j++) acc[i][j] += a[i] * b[j];
        }
        __syncthreads();
    }
#pragma unroll
    for (int i = 0; i < 4; i++) {
        int gr = rowBase + tr * 4 + i;
        if (gr < M)
#pragma unroll
            for (int j = 0; j < 4; j++) C[gr * 64 + tc * 4 + j] = acc[i][j];
    }
}

// ---------------------------------------------------------------------------
// CSR aggregation over 64 features: out[d] = sum_{s in N(d)} h[s]*dinv[s]*dinv[d]
//                                           + h[d]*dinv[d]^2  (+bias, relu?)
// One warp per node; lane handles features {l, l+32}.
// ---------------------------------------------------------------------------
__global__ void k_agg64(const float* __restrict__ h,
                        const float* __restrict__ bias,
                        float* __restrict__ out, int n, int relu) {
    int node = blockIdx.x * 8 + (threadIdx.x >> 5);
    if (node >= n) return;
    int lane = threadIdx.x & 31;
    float dn = g_dinv[node];
    float a0 = h[node * 64 + lane] * dn * dn;
    float a1 = h[node * 64 + 32 + lane] * dn * dn;
    int beg = g_off[node], end = g_off[node + 1];
    for (int p = beg; p < end; p++) {
        int s = g_esrc[p];
        float w = g_dinv[s] * dn;
        a0 += h[s * 64 + lane] * w;
        a1 += h[s * 64 + 32 + lane] * w;
    }
    if (bias) { a0 += bias[lane]; a1 += bias[32 + lane]; }
    if (relu) { a0 = fmaxf(a0, 0.0f); a1 = fmaxf(a1, 0.0f); }
    out[node * 64 + lane] = a0;
    out[node * 64 + 32 + lane] = a1;
}

// ---------------------------------------------------------------------------
// Fused mid: z = h1@Wef+bef (write out); hd = relu(z@Wdf+bdf); pred = z@Wc+bc
// 16 rows per block, all weights in SMEM.
// ---------------------------------------------------------------------------
__global__ void k_fused_mid(const float* __restrict__ h1,
                            const float* __restrict__ Wef, const float* __restrict__ bef,
                            const float* __restrict__ Wdf, const float* __restrict__ bdf,
                            const float* __restrict__ Wc,  const float* __restrict__ bc,
                            float* __restrict__ z_out, float* __restrict__ hd_out,
                            float* __restrict__ pred_out, int n) {
    __shared__ float sWef[64 * 32];
    __shared__ float sWdf[32 * 64];
    __shared__ float sWc[32 * 3];
    __shared__ float sbef[32], sbdf[64], sbc[3];
    __shared__ float sh[16][64];
    __shared__ float sz[16][32];
    int tid = threadIdx.x;  // 256
    for (int i = tid; i < 64 * 32; i += 256) sWef[i] = Wef[i];
    for (int i = tid; i < 32 * 64; i += 256) sWdf[i] = Wdf[i];
    for (int i = tid; i < 32 * 3; i += 256) sWc[i] = Wc[i];
    if (tid < 32) sbef[tid] = bef[tid];
    if (tid < 64) sbdf[tid] = bdf[tid];
    if (tid < 3)  sbc[tid]  = bc[tid];
    int rowBase = blockIdx.x * 16;
    for (int i = tid; i < 16 * 64; i += 256) {
        int r = i >> 6, c = i & 63;
        int gr = rowBase + r;
        sh[r][c] = (gr < n) ? h1[gr * 64 + c] : 0.0f;
    }
    __syncthreads();
    // z: 16x32
    for (int o = tid; o < 512; o += 256) {
        int r = o >> 5, j = o & 31;
        float acc = sbef[j];
#pragma unroll
        for (int k = 0; k < 64; k++) acc += sh[r][k] * sWef[k * 32 + j];
        sz[r][j] = acc;
        int gr = rowBase + r;
        if (gr < n) z_out[gr * 32 + j] = acc;
    }
    __syncthreads();
    // hd: 16x64
    for (int o = tid; o < 1024; o += 256) {
        int r = o >> 6, j = o & 63;
        float acc = sbdf[j];
#pragma unroll
        for (int k = 0; k < 32; k++) acc += sz[r][k] * sWdf[k * 64 + j];
        acc = fmaxf(acc, 0.0f);
        int gr = rowBase + r;
        if (gr < n) hd_out[gr * 64 + j] = acc;
    }
    // pred: 16x3
    for (int o = tid; o < 48; o += 256) {
        int r = o / 3, j = o % 3;
        float acc = sbc[j];
#pragma unroll
        for (int k = 0; k < 32; k++) acc += sz[r][k] * sWc[k * 3 + j];
        int gr = rowBase + r;
        if (gr < n) pred_out[gr * 3 + j] = acc;
    }
}

// ---------------------------------------------------------------------------
// GEMM: [M,64] @ [64,256] + bias -> [M,256]   (x_recon = a2 @ W_dec_gnn + b)
// 32 rows per block; thread owns one output column.
// ---------------------------------------------------------------------------
__global__ void k_gemm_64_256(const float* __restrict__ A,
                              const float* __restrict__ W,
                              const float* __restrict__ bias,
                              float* __restrict__ C, int M) {
    __shared__ float Ws[32][256];
    __shared__ float As[32][33];
    int tid = threadIdx.x;  // 256
    int rowBase = blockIdx.x * 32;
    float acc[32];
#pragma unroll
    for (int i = 0; i < 32; i++) acc[i] = 0.0f;
    for (int k0 = 0; k0 < 64; k0 += 32) {
        for (int i = tid; i < 32 * 256; i += 256) {
            int r = i >> 8, c = i & 255;
            Ws[r][c] = W[(k0 + r) * 256 + c];
        }
        for (int i = tid; i < 32 * 32; i += 256) {
            int r = i >> 5, c = i & 31;
            int gr = rowBase + r;
            As[r][c] = (gr < M) ? A[gr * 64 + k0 + c] : 0.0f;
        }
        __syncthreads();
#pragma unroll
        for (int k = 0; k < 32; k++) {
            float w = Ws[k][tid];
#pragma unroll
            for (int r = 0; r < 32; r++) acc[r] += As[r][k] * w;
        }
        __syncthreads();
    }
    float b = bias[tid];
#pragma unroll
    for (int r = 0; r < 32; r++) {
        int gr = rowBase + r;
        if (gr < M) C[gr * 256 + tid] = acc[r] + b;
    }
}

// ---------------------------------------------------------------------------
// Host launch
// ---------------------------------------------------------------------------
extern "C" void kernel_launch(void* const* d_in, const int* in_sizes, int n_in,
                              void* d_out, int out_size) {
    const float* x         = (const float*)d_in[0];   // [N,256]
    const int*   edge_idx  = (const int*)d_in[1];     // [2,E]
    // d_in[2] = edge_attr (unused by reference)
    const float* W_enc_gnn = (const float*)d_in[3];   // [256,64]
    const float* b_enc_gnn = (const float*)d_in[4];   // [64]
    const float* W_enc_fc  = (const float*)d_in[5];   // [64,32]
    const float* b_enc_fc  = (const float*)d_in[6];   // [32]
    const float* W_dec_fc  = (const float*)d_in[7];   // [32,64]
    const float* b_dec_fc  = (const float*)d_in[8];   // [64]
    const float* W_dec_gnn = (const float*)d_in[9];   // [64,256]
    const float* b_dec_gnn = (const float*)d_in[10];  // [256]
    const float* W_cond    = (const float*)d_in[11];  // [32,3]
    const float* b_cond    = (const float*)d_in[12];  // [3]

    int N = in_sizes[0] / 256;
    int E = in_sizes[2];
    const int* src = edge_idx;
    const int* dst = edge_idx + E;

    float* out_xrecon = (float*)d_out;                  // [N,256]
    float* out_z      = out_xrecon + (size_t)N * 256;   // [N,32]
    float* out_pred   = out_z + (size_t)N * 32;         // [N,3]

    // symbol addresses for scratch
    float *p_h1pre, *p_h1, *p_hd, *p_a2;
    cudaGetSymbolAddress((void**)&p_h1pre, g_h1pre);
    cudaGetSymbolAddress((void**)&p_h1,    g_h1);
    cudaGetSymbolAddress((void**)&p_hd,    g_hd);
    cudaGetSymbolAddress((void**)&p_a2,    g_a2);

    int nbN  = (N + 255) / 256;
    int nbE  = (E + 255) / 256;
    int nbSc = (N + 1023) / 1024;

    // CSR + normalization
    k_init<<<nbN, 256>>>(N);
    k_count<<<nbE, 256>>>(dst, E);
    k_dinv<<<nbN, 256>>>(N);
    k_scan_bsum<<<nbSc, 1024>>>(N);
    k_scan_sums<<<1, 1024>>>(nbSc);
    k_scan_final<<<nbSc, 1024>>>(N, E);
    k_fill<<<nbE, 256>>>(src, dst, E);

    // encoder conv: transform then aggregate
    k_gemm_256_64<<<(N + 63) / 64, 256>>>(x, W_enc_gnn, p_h1pre, N);
    k_agg64<<<(N + 7) / 8, 256>>>(p_h1pre, b_enc_gnn, p_h1, N, 1);

    // fused z / hd / pred
    k_fused_mid<<<(N + 15) / 16, 256>>>(p_h1, W_enc_fc, b_enc_fc,
                                        W_dec_fc, b_dec_fc, W_cond, b_cond,
                                        out_z, p_hd, out_pred, N);

    // decoder conv: aggregate FIRST (linearity), then transform (4x less gather)
    k_agg64<<<(N + 7) / 8, 256>>>(p_hd, (const float*)nullptr, p_a2, N, 0);
    k_gemm_64_256<<<(N + 31) / 32, 256>>>(p_a2, W_dec_gnn, b_dec_gnn, out_xrecon, N);
}

// round 2
// speedup vs baseline: 1.0859x; 1.0859x over previous
#include <cuda_runtime.h>
#include <math.h>

#define NMAX 50048
#define EMAX 800000

// Scratch (device globals: no allocation allowed)
__device__ float g_h1pre[NMAX * 64];
__device__ float g_h1[NMAX * 64];
__device__ float g_hd[NMAX * 64];
__device__ float g_a2[NMAX * 64];
__device__ float g_dinv[NMAX];
__device__ int   g_cnt[NMAX];
__device__ int   g_cur[NMAX];
__device__ int   g_off[NMAX + 1];
__device__ int   g_esrc[EMAX];
__device__ int   g_bsums[128];

// packed f32x2 FMA: d = a*b + d (lanewise on 2 packed floats)
__device__ __forceinline__ void fma2(unsigned long long &d,
                                     unsigned long long a,
                                     unsigned long long b) {
    asm("fma.rn.f32x2 %0, %1, %2, %0;" : "+l"(d) : "l"(a), "l"(b));
}
__device__ __forceinline__ float f2lo(unsigned long long v) {
    return __uint_as_float((unsigned)(v & 0xffffffffu));
}
__device__ __forceinline__ float f2hi(unsigned long long v) {
    return __uint_as_float((unsigned)(v >> 32));
}

// ---------------------------------------------------------------------------
// CSR build
// ---------------------------------------------------------------------------
__global__ void k_count(const int* __restrict__ dst, int E) {
    int e = blockIdx.x * blockDim.x + threadIdx.x;
    if (e < E) atomicAdd(&g_cnt[dst[e]], 1);
}

__global__ void k_scan_bsum(int n) {
    __shared__ int s[1024];
    int i = blockIdx.x * 1024 + threadIdx.x;
    s[threadIdx.x] = (i < n) ? g_cnt[i] : 0;
    __syncthreads();
    for (int st = 512; st > 0; st >>= 1) {
        if (threadIdx.x < st) s[threadIdx.x] += s[threadIdx.x + st];
        __syncthreads();
    }
    if (threadIdx.x == 0) g_bsums[blockIdx.x] = s[0];
}

__global__ void k_scan_sums(int nb) {
    __shared__ int s[1024];
    int v = (threadIdx.x < nb) ? g_bsums[threadIdx.x] : 0;
    s[threadIdx.x] = v;
    __syncthreads();
    for (int st = 1; st < 1024; st <<= 1) {
        int t = (threadIdx.x >= st) ? s[threadIdx.x - st] : 0;
        __syncthreads();
        s[threadIdx.x] += t;
        __syncthreads();
    }
    if (threadIdx.x < nb) g_bsums[threadIdx.x] = s[threadIdx.x] - v;
}

// exclusive offsets + dinv + cur reset (fused)
__global__ void k_scan_final(int n, int E) {
    __shared__ int s[1024];
    int i = blockIdx.x * 1024 + threadIdx.x;
    int v = (i < n) ? g_cnt[i] : 0;
    s[threadIdx.x] = v;
    __syncthreads();
    for (int st = 1; st < 1024; st <<= 1) {
        int t = (threadIdx.x >= st) ? s[threadIdx.x - st] : 0;
        __syncthreads();
        s[threadIdx.x] += t;
        __syncthreads();
    }
    if (i < n) {
        g_off[i]  = g_bsums[blockIdx.x] + s[threadIdx.x] - v;
        g_dinv[i] = rsqrtf(1.0f + (float)v);
        g_cur[i]  = 0;
    }
    if (i == 0) g_off[n] = E;
}

__global__ void k_fill(const int* __restrict__ src, const int* __restrict__ dst, int E) {
    int e = blockIdx.x * blockDim.x + threadIdx.x;
    if (e < E) {
        int d = dst[e];
        int pos = g_off[d] + atomicAdd(&g_cur[d], 1);
        g_esrc[pos] = src[e];
    }
}

// ---------------------------------------------------------------------------
// GEMM1: [M,256] @ [256,64] -> [M,64]  (f32x2 packed, A duplicated in SMEM)
// block: 128 rows x 64 cols, 256 threads, thread tile 8 rows x 4 cols (2 pairs)
// ---------------------------------------------------------------------------
__global__ void __launch_bounds__(256) k_gemm_256_64(
    const float* __restrict__ A, const float* __restrict__ W,
    float* __restrict__ C, int M) {
    __shared__ float2 Asd[32][129];   // [k][row] duplicated (a,a); pad 129
    __shared__ float2 Wp[32][33];     // [k][colpair]; pad 33
    const int tid = threadIdx.x;
    const int tc = tid & 15;          // col-group (4 cols)
    const int tr = tid >> 4;          // row-group (8 rows)
    const int rowBase = blockIdx.x * 128;
    const float2* __restrict__ W2 = (const float2*)W;

    unsigned long long acc[8][2];
#pragma unroll
    for (int i = 0; i < 8; i++) { acc[i][0] = 0ull; acc[i][1] = 0ull; }

    for (int k0 = 0; k0 < 256; k0 += 32) {
        // load A panel: 32 k x 128 rows, coalesced over k
#pragma unroll
        for (int j = 0; j < 16; j++) {
            int i = tid + j * 256;
            int k = i & 31, r = i >> 5;
            int gr = rowBase + r;
            float v = (gr < M) ? A[gr * 256 + k0 + k] : 0.0f;
            Asd[k][r] = make_float2(v, v);
        }
        // load W panel: 32 k x 32 pairs
#pragma unroll
        for (int j = 0; j < 4; j++) {
            int i = tid + j * 256;
            int c2 = i & 31, k = i >> 5;
            Wp[k][c2] = W2[(k0 + k) * 32 + c2];
        }
        __syncthreads();
#pragma unroll
        for (int k = 0; k < 32; k++) {
            unsigned long long b0 = *(const unsigned long long*)&Wp[k][tc * 2];
            unsigned long long b1 = *(const unsigned long long*)&Wp[k][tc * 2 + 1];
            unsigned long long a[8];
#pragma unroll
            for (int i = 0; i < 8; i++)
                a[i] = *(const unsigned long long*)&Asd[k][tr * 8 + i];
#pragma unroll
            for (int i = 0; i < 8; i++) {
                fma2(acc[i][0], a[i], b0);
                fma2(acc[i][1], a[i], b1);
            }
        }
        __syncthreads();
    }
#pragma unroll
    for (int i = 0; i < 8; i++) {
        int gr = rowBase + tr * 8 + i;
        if (gr < M) {
            float4 o = make_float4(f2lo(acc[i][0]), f2hi(acc[i][0]),
                                   f2lo(acc[i][1]), f2hi(acc[i][1]));
            *(float4*)&C[gr * 64 + tc * 4] = o;
        }
    }
}

// ---------------------------------------------------------------------------
// GEMM2: [M,64] @ [64,256] + bias -> [M,256]  (f32x2 packed)
// block: 32 rows x 256 cols, 256 threads, thread tile 8 rows x 4 cols
// ---------------------------------------------------------------------------
__global__ void __launch_bounds__(256) k_gemm_64_256(
    const float* __restrict__ A, const float* __restrict__ W,
    const float* __restrict__ bias, float* __restrict__ C, int M) {
    __shared__ float2 Asd[32][33];    // [k][row] duplicated
    __shared__ float2 Wp[32][129];    // [k][colpair] (128 pairs)
    const int tid = threadIdx.x;
    const int tc = tid & 63;          // col-group (4 cols of 256)
    const int tr = tid >> 6;          // row-group (8 rows of 32)
    const int rowBase = blockIdx.x * 32;
    const float2* __restrict__ W2 = (const float2*)W;

    unsigned long long acc[8][2];
#pragma unroll
    for (int i = 0; i < 8; i++) { acc[i][0] = 0ull; acc[i][1] = 0ull; }

    for (int k0 = 0; k0 < 64; k0 += 32) {
        // A panel: 32 k x 32 rows
#pragma unroll
        for (int j = 0; j < 4; j++) {
            int i = tid + j * 256;
            int k = i & 31, r = i >> 5;
            int gr = rowBase + r;
            float v = (gr < M) ? A[gr * 64 + k0 + k] : 0.0f;
            Asd[k][r] = make_float2(v, v);
        }
        // W panel: 32 k x 128 pairs
#pragma unroll
        for (int j = 0; j < 16; j++) {
            int i = tid + j * 256;
            int c2 = i & 127, k = i >> 7;
            Wp[k][c2] = W2[(k0 + k) * 128 + c2];
        }
        __syncthreads();
#pragma unroll
        for (int k = 0; k < 32; k++) {
            unsigned long long b0 = *(const unsigned long long*)&Wp[k][tc * 2];
            unsigned long long b1 = *(const unsigned long long*)&Wp[k][tc * 2 + 1];
            unsigned long long a[8];
#pragma unroll
            for (int i = 0; i < 8; i++)
                a[i] = *(const unsigned long long*)&Asd[k][tr * 8 + i];
#pragma unroll
            for (int i = 0; i < 8; i++) {
                fma2(acc[i][0], a[i], b0);
                fma2(acc[i][1], a[i], b1);
            }
        }
        __syncthreads();
    }
    float4 bv = *(const float4*)&bias[tc * 4];
#pragma unroll
    for (int i = 0; i < 8; i++) {
        int gr = rowBase + tr * 8 + i;
        if (gr < M) {
            float4 o = make_float4(f2lo(acc[i][0]) + bv.x, f2hi(acc[i][0]) + bv.y,
                                   f2lo(acc[i][1]) + bv.z, f2hi(acc[i][1]) + bv.w);
            *(float4*)&C[gr * 256 + tc * 4] = o;
        }
    }
}

// ---------------------------------------------------------------------------
// CSR aggregation, 64 feats: warp per node, lane owns feature-pair (float2)
// ---------------------------------------------------------------------------
__global__ void k_agg64(const float* __restrict__ h,
                        const float* __restrict__ bias,
                        float* __restrict__ out, int n, int relu) {
    int node = blockIdx.x * 8 + (threadIdx.x >> 5);
    if (node >= n) return;
    int lane = threadIdx.x & 31;
    const float2* __restrict__ h2 = (const float2*)h;
    float dn = g_dinv[node];
    float2 self = h2[node * 32 + lane];
    float ax = self.x * dn * dn;
    float ay = self.y * dn * dn;
    int p = g_off[node], end = g_off[node + 1];
    for (; p + 1 < end; p += 2) {
        int s0 = g_esrc[p], s1 = g_esrc[p + 1];
        float w0 = g_dinv[s0] * dn, w1 = g_dinv[s1] * dn;
        float2 v0 = h2[s0 * 32 + lane];
        float2 v1 = h2[s1 * 32 + lane];
        ax += v0.x * w0 + v1.x * w1;
        ay += v0.y * w0 + v1.y * w1;
    }
    if (p < end) {
        int s = g_esrc[p];
        float w = g_dinv[s] * dn;
        float2 v = h2[s * 32 + lane];
        ax += v.x * w;
        ay += v.y * w;
    }
    if (bias) {
        const float2* b2 = (const float2*)bias;
        float2 b = b2[lane];
        ax += b.x; ay += b.y;
    }
    if (relu) { ax = fmaxf(ax, 0.0f); ay = fmaxf(ay, 0.0f); }
    ((float2*)out)[node * 32 + lane] = make_float2(ax, ay);
}

// ---------------------------------------------------------------------------
// Fused mid: z = h1@Wef+bef; hd = relu(z@Wdf+bdf); pred = z@Wc+bc
// ---------------------------------------------------------------------------
__global__ void k_fused_mid(const float* __restrict__ h1,
                            const float* __restrict__ Wef, const float* __restrict__ bef,
                            const float* __restrict__ Wdf, const float* __restrict__ bdf,
                            const float* __restrict__ Wc,  const float* __restrict__ bc,
                            float* __restrict__ z_out, float* __restrict__ hd_out,
                            float* __restrict__ pred_out, int n) {
    __shared__ float sWef[64 * 32];
    __shared__ float sWdf[32 * 64];
    __shared__ float sWc[32 * 3];
    __shared__ float sbef[32], sbdf[64], sbc[3];
    __shared__ float sh[16][64];
    __shared__ float sz[16][32];
    int tid = threadIdx.x;  // 256
    for (int i = tid; i < 64 * 32; i += 256) sWef[i] = Wef[i];
    for (int i = tid; i < 32 * 64; i += 256) sWdf[i] = Wdf[i];
    for (int i = tid; i < 32 * 3; i += 256) sWc[i] = Wc[i];
    if (tid < 32) sbef[tid] = bef[tid];
    if (tid < 64) sbdf[tid] = bdf[tid];
    if (tid < 3)  sbc[tid]  = bc[tid];
    int rowBase = blockIdx.x * 16;
    for (int i = tid; i < 16 * 64; i += 256) {
        int r = i >> 6, c = i & 63;
        int gr = rowBase + r;
        sh[r][c] = (gr < n) ? h1[gr * 64 + c] : 0.0f;
    }
    __syncthreads();
    for (int o = tid; o < 512; o += 256) {
        int r = o >> 5, j = o & 31;
        float acc = sbef[j];
#pragma unroll
        for (int k = 0; k < 64; k++) acc += sh[r][k] * sWef[k * 32 + j];
        sz[r][j] = acc;
        int gr = rowBase + r;
        if (gr < n) z_out[gr * 32 + j] = acc;
    }
    __syncthreads();
    for (int o = tid; o < 1024; o += 256) {
        int r = o >> 6, j = o & 63;
        float acc = sbdf[j];
#pragma unroll
        for (int k = 0; k < 32; k++) acc += sz[r][k] * sWdf[k * 64 + j];
        acc = fmaxf(acc, 0.0f);
        int gr = rowBase + r;
        if (gr < n) hd_out[gr * 64 + j] = acc;
    }
    for (int o = tid; o < 48; o += 256) {
        int r = o / 3, j = o % 3;
        float acc = sbc[j];
#pragma unroll
        for (int k = 0; k < 32; k++) acc += sz[r][k] * sWc[k * 3 + j];
        int gr = rowBase + r;
        if (gr < n) pred_out[gr * 3 + j] = acc;
    }
}

// ---------------------------------------------------------------------------
// Host launch
// ---------------------------------------------------------------------------
extern "C" void kernel_launch(void* const* d_in, const int* in_sizes, int n_in,
                              void* d_out, int out_size) {
    const float* x         = (const float*)d_in[0];
    const int*   edge_idx  = (const int*)d_in[1];
    const float* W_enc_gnn = (const float*)d_in[3];
    const float* b_enc_gnn = (const float*)d_in[4];
    const float* W_enc_fc  = (const float*)d_in[5];
    const float* b_enc_fc  = (const float*)d_in[6];
    const float* W_dec_fc  = (const float*)d_in[7];
    const float* b_dec_fc  = (const float*)d_in[8];
    const float* W_dec_gnn = (const float*)d_in[9];
    const float* b_dec_gnn = (const float*)d_in[10];
    const float* W_cond    = (const float*)d_in[11];
    const float* b_cond    = (const float*)d_in[12];

    int N = in_sizes[0] / 256;
    int E = in_sizes[2];
    const int* src = edge_idx;
    const int* dst = edge_idx + E;

    float* out_xrecon = (float*)d_out;
    float* out_z      = out_xrecon + (size_t)N * 256;
    float* out_pred   = out_z + (size_t)N * 32;

    float *p_h1pre, *p_h1, *p_hd, *p_a2;
    int *p_cnt;
    cudaGetSymbolAddress((void**)&p_h1pre, g_h1pre);
    cudaGetSymbolAddress((void**)&p_h1,    g_h1);
    cudaGetSymbolAddress((void**)&p_hd,    g_hd);
    cudaGetSymbolAddress((void**)&p_a2,    g_a2);
    cudaGetSymbolAddress((void**)&p_cnt,   g_cnt);

    int nbE  = (E + 255) / 256;
    int nbSc = (N + 1023) / 1024;

    cudaMemsetAsync(p_cnt, 0, (size_t)N * sizeof(int), 0);
    k_count<<<nbE, 256>>>(dst, E);
    k_scan_bsum<<<nbSc, 1024>>>(N);
    k_scan_sums<<<1, 1024>>>(nbSc);
    k_scan_final<<<nbSc, 1024>>>(N, E);   // + dinv + cur reset
    k_fill<<<nbE, 256>>>(src, dst, E);

    k_gemm_256_64<<<(N + 127) / 128, 256>>>(x, W_enc_gnn, p_h1pre, N);
    k_agg64<<<(N + 7) / 8, 256>>>(p_h1pre, b_enc_gnn, p_h1, N, 1);

    k_fused_mid<<<(N + 15) / 16, 256>>>(p_h1, W_enc_fc, b_enc_fc,
                                        W_dec_fc, b_dec_fc, W_cond, b_cond,
                                        out_z, p_hd, out_pred, N);

    k_agg64<<<(N + 7) / 8, 256>>>(p_hd, (const float*)nullptr, p_a2, N, 0);
    k_gemm_64_256<<<(N + 31) / 32, 256>>>(p_a2, W_dec_gnn, b_dec_gnn, out_xrecon, N);
}

// round 5
// speedup vs baseline: 1.5209x; 1.4005x over previous
#include <cuda_runtime.h>
#include <cuda_bf16.h>
#include <math.h>
#include <stdint.h>

#define NMAX 50048
#define EMAX 800000

// Scratch (device globals: no allocation allowed)
__device__ float g_h1pre[NMAX * 64];
__device__ float g_h1[NMAX * 64];
__device__ float g_hd[NMAX * 64];
__device__ float g_a2[NMAX * 64];
__device__ float g_dinv[NMAX];
__device__ int   g_cnt[NMAX];
__device__ int   g_cur[NMAX];
__device__ int   g_off[NMAX + 1];
__device__ int   g_esrc[EMAX];
__device__ int   g_bsums[128];
// bf16 split weights: W1T = W_enc_gnn^T [64 n][256 k], W2T = W_dec_gnn^T [256 n][64 k]
__device__ __nv_bfloat16 g_w1t_hi[64 * 256];
__device__ __nv_bfloat16 g_w1t_lo[64 * 256];
__device__ __nv_bfloat16 g_w2t_hi[256 * 64];
__device__ __nv_bfloat16 g_w2t_lo[256 * 64];

__device__ __forceinline__ uint32_t pack2bf(float a, float b) {
    __nv_bfloat162 t = __floats2bfloat162_rn(a, b);
    return *(uint32_t*)&t;
}
__device__ __forceinline__ float bf_hi_f(float a) {
    return __bfloat162float(__float2bfloat16_rn(a));
}

// mma.sync m16n8k16 bf16 -> f32 accum (portable PTX, lowers to HMMA)
__device__ __forceinline__ void mma16816(float* d, const uint32_t* a, const uint32_t* b) {
    asm volatile(
        "mma.sync.aligned.m16n8k16.row.col.f32.bf16.bf16.f32 "
        "{%0,%1,%2,%3}, {%4,%5,%6,%7}, {%8,%9}, {%0,%1,%2,%3};"
        : "+f"(d[0]), "+f"(d[1]), "+f"(d[2]), "+f"(d[3])
        : "r"(a[0]), "r"(a[1]), "r"(a[2]), "r"(a[3]), "r"(b[0]), "r"(b[1]));
}

// ---------------------------------------------------------------------------
// CSR build
// ---------------------------------------------------------------------------
__global__ void k_count(const int* __restrict__ dst, int E) {
    int e = blockIdx.x * blockDim.x + threadIdx.x;
    if (e < E) atomicAdd(&g_cnt[dst[e]], 1);
}
__global__ void k_scan_bsum(int n) {
    __shared__ int s[1024];
    int i = blockIdx.x * 1024 + threadIdx.x;
    s[threadIdx.x] = (i < n) ? g_cnt[i] : 0;
    __syncthreads();
    for (int st = 512; st > 0; st >>= 1) {
        if (threadIdx.x < st) s[threadIdx.x] += s[threadIdx.x + st];
        __syncthreads();
    }
    if (threadIdx.x == 0) g_bsums[blockIdx.x] = s[0];
}
__global__ void k_scan_sums(int nb) {
    __shared__ int s[1024];
    int v = (threadIdx.x < nb) ? g_bsums[threadIdx.x] : 0;
    s[threadIdx.x] = v;
    __syncthreads();
    for (int st = 1; st < 1024; st <<= 1) {
        int t = (threadIdx.x >= st) ? s[threadIdx.x - st] : 0;
        __syncthreads();
        s[threadIdx.x] += t;
        __syncthreads();
    }
    if (threadIdx.x < nb) g_bsums[threadIdx.x] = s[threadIdx.x] - v;
}
__global__ void k_scan_final(int n, int E) {
    __shared__ int s[1024];
    int i = blockIdx.x * 1024 + threadIdx.x;
    int v = (i < n) ? g_cnt[i] : 0;
    s[threadIdx.x] = v;
    __syncthreads();
    for (int st = 1; st < 1024; st <<= 1) {
        int t = (threadIdx.x >= st) ? s[threadIdx.x - st] : 0;
        __syncthreads();
        s[threadIdx.x] += t;
        __syncthreads();
    }
    if (i < n) {
        g_off[i]  = g_bsums[blockIdx.x] + s[threadIdx.x] - v;
        g_dinv[i] = rsqrtf(1.0f + (float)v);
        g_cur[i]  = 0;
    }
    if (i == 0) g_off[n] = E;
}
__global__ void k_fill(const int* __restrict__ src, const int* __restrict__ dst, int E) {
    int e = blockIdx.x * blockDim.x + threadIdx.x;
    if (e < E) {
        int d = dst[e];
        int pos = g_off[d] + atomicAdd(&g_cur[d], 1);
        g_esrc[pos] = src[e];
    }
}

// ---------------------------------------------------------------------------
// Weight transpose + bf16 hi/lo split
// ---------------------------------------------------------------------------
__global__ void k_wconv(const float* __restrict__ W1, const float* __restrict__ W2) {
    int i = blockIdx.x * blockDim.x + threadIdx.x;
    if (i < 64 * 256) {            // W1T[n][k] = W1[k][n]
        int n = i >> 8, k = i & 255;
        float v = W1[k * 64 + n];
        float h = bf_hi_f(v);
        g_w1t_hi[i] = __float2bfloat16_rn(h);
        g_w1t_lo[i] = __float2bfloat16_rn(v - h);
    } else if (i < 2 * 64 * 256) { // W2T[n][k] = W2[k][n]
        int t = i - 64 * 256;
        int n = t >> 6, k = t & 63;
        float v = W2[k * 256 + n];
        float h = bf_hi_f(v);
        g_w2t_hi[t] = __float2bfloat16_rn(h);
        g_w2t_lo[t] = __float2bfloat16_rn(v - h);
    }
}

// ---------------------------------------------------------------------------
// GEMM1 (mma.sync): [M,256]fp32 @ W1 -> [M,64]fp32, block = 128 rows x 64 cols
// smem (bf16, row pad 72): Ah[128][72], Al[128][72], Bh[64][72], Bl[64][72]
// K processed in 4 chunks of 64.
// ---------------------------------------------------------------------------
#define G1_LDA 72
#define G1_AH  0
#define G1_AL  (128 * 72)
#define G1_BH  (2 * 128 * 72)
#define G1_BL  (2 * 128 * 72 + 64 * 72)
#define G1_SMEM ((2 * 128 * 72 + 2 * 64 * 72) * 2)

__global__ void __launch_bounds__(256) k_mma_gemm1(
    const float* __restrict__ A, float* __restrict__ C, int M) {
    extern __shared__ __align__(16) uint16_t sm1[];
    const int tid = threadIdx.x;
    const int wid = tid >> 5, lane = tid & 31;
    const int g = lane >> 2, tig = lane & 3;
    const int rowBase = blockIdx.x * 128;
    const int warpRow = wid * 16;

    float acc[8][4];
#pragma unroll
    for (int i = 0; i < 8; i++)
#pragma unroll
        for (int j = 0; j < 4; j++) acc[i][j] = 0.0f;

    for (int kc0 = 0; kc0 < 256; kc0 += 64) {
        // stage A chunk: 128 rows x 64 k (8 floats per thread-chunk)
#pragma unroll
        for (int i = 0; i < 4; i++) {
            int c = tid + i * 256;
            int r = c >> 3, k8 = (c & 7) * 8;
            int gr = rowBase + r;
            float4 f0, f1;
            if (gr < M) {
                f0 = *(const float4*)&A[(size_t)gr * 256 + kc0 + k8];
                f1 = *(const float4*)&A[(size_t)gr * 256 + kc0 + k8 + 4];
            } else { f0 = make_float4(0, 0, 0, 0); f1 = f0; }
            float h0 = bf_hi_f(f0.x), h1 = bf_hi_f(f0.y), h2 = bf_hi_f(f0.z), h3 = bf_hi_f(f0.w);
            float h4 = bf_hi_f(f1.x), h5 = bf_hi_f(f1.y), h6 = bf_hi_f(f1.z), h7 = bf_hi_f(f1.w);
            uint4 hv = make_uint4(pack2bf(h0, h1), pack2bf(h2, h3), pack2bf(h4, h5), pack2bf(h6, h7));
            uint4 lv = make_uint4(pack2bf(f0.x - h0, f0.y - h1), pack2bf(f0.z - h2, f0.w - h3),
                                  pack2bf(f1.x - h4, f1.y - h5), pack2bf(f1.z - h6, f1.w - h7));
            *(uint4*)&sm1[G1_AH + r * G1_LDA + k8] = hv;
            *(uint4*)&sm1[G1_AL + r * G1_LDA + k8] = lv;
        }
        // stage B chunk: 64 n x 64 k
#pragma unroll
        for (int i = 0; i < 2; i++) {
            int c = tid + i * 256;
            int n = c >> 3, k8 = (c & 7) * 8;
            *(uint4*)&sm1[G1_BH + n * G1_LDA + k8] = *(const uint4*)&g_w1t_hi[n * 256 + kc0 + k8];
            *(uint4*)&sm1[G1_BL + n * G1_LDA + k8] = *(const uint4*)&g_w1t_lo[n * 256 + kc0 + k8];
        }
        __syncthreads();
#pragma unroll
        for (int ks = 0; ks < 4; ks++) {
            int col0 = ks * 16 + 2 * tig;
            int col1 = col0 + 8;
            int row0 = warpRow + g, row1 = row0 + 8;
            uint32_t ah[4], al[4];
            ah[0] = *(uint32_t*)&sm1[G1_AH + row0 * G1_LDA + col0];
            ah[1] = *(uint32_t*)&sm1[G1_AH + row1 * G1_LDA + col0];
            ah[2] = *(uint32_t*)&sm1[G1_AH + row0 * G1_LDA + col1];
            ah[3] = *(uint32_t*)&sm1[G1_AH + row1 * G1_LDA + col1];
            al[0] = *(uint32_t*)&sm1[G1_AL + row0 * G1_LDA + col0];
            al[1] = *(uint32_t*)&sm1[G1_AL + row1 * G1_LDA + col0];
            al[2] = *(uint32_t*)&sm1[G1_AL + row0 * G1_LDA + col1];
            al[3] = *(uint32_t*)&sm1[G1_AL + row1 * G1_LDA + col1];
#pragma unroll
            for (int nt = 0; nt < 8; nt++) {
                int nr = nt * 8 + g;
                uint32_t bh[2], bl[2];
                bh[0] = *(uint32_t*)&sm1[G1_BH + nr * G1_LDA + col0];
                bh[1] = *(uint32_t*)&sm1[G1_BH + nr * G1_LDA + col1];
                bl[0] = *(uint32_t*)&sm1[G1_BL + nr * G1_LDA + col0];
                bl[1] = *(uint32_t*)&sm1[G1_BL + nr * G1_LDA + col1];
                mma16816(acc[nt], ah, bh);
                mma16816(acc[nt], ah, bl);
                mma16816(acc[nt], al, bh);
            }
        }
        __syncthreads();
    }
    int gr0 = rowBase + warpRow + g;
    int gr1 = gr0 + 8;
#pragma unroll
    for (int nt = 0; nt < 8; nt++) {
        int col = nt * 8 + 2 * tig;
        if (gr0 < M) *(float2*)&C[(size_t)gr0 * 64 + col] = make_float2(acc[nt][0], acc[nt][1]);
        if (gr1 < M) *(float2*)&C[(size_t)gr1 * 64 + col] = make_float2(acc[nt][2], acc[nt][3]);
    }
}

// ---------------------------------------------------------------------------
// GEMM2 (mma.sync): [M,64]fp32 @ W2 + bias -> [M,256]fp32
// block = 64 rows x 256 cols; warp = 16 rows x 128 cols (rg = wid&3, ng = wid>>2)
// smem: Ah[64][72], Al[64][72], Bh[256][72], Bl[256][72]
// ---------------------------------------------------------------------------
#define G2_LDA 72
#define G2_AH  0
#define G2_AL  (64 * 72)
#define G2_BH  (2 * 64 * 72)
#define G2_BL  (2 * 64 * 72 + 256 * 72)
#define G2_SMEM ((2 * 64 * 72 + 2 * 256 * 72) * 2)

__global__ void __launch_bounds__(256) k_mma_gemm2(
    const float* __restrict__ A, const float* __restrict__ bias,
    float* __restrict__ C, int M) {
    extern __shared__ __align__(16) uint16_t sm2[];
    const int tid = threadIdx.x;
    const int wid = tid >> 5, lane = tid & 31;
    const int g = lane >> 2, tig = lane & 3;
    const int rowBase = blockIdx.x * 64;
    const int warpRow = (wid & 3) * 16;
    const int warpCol = (wid >> 2) * 128;

    // stage A: 64 rows x 64 k
#pragma unroll
    for (int i = 0; i < 2; i++) {
        int c = tid + i * 256;
        int r = c >> 3, k8 = (c & 7) * 8;
        int gr = rowBase + r;
        float4 f0, f1;
        if (gr < M) {
            f0 = *(const float4*)&A[(size_t)gr * 64 + k8];
            f1 = *(const float4*)&A[(size_t)gr * 64 + k8 + 4];
        } else { f0 = make_float4(0, 0, 0, 0); f1 = f0; }
        float h0 = bf_hi_f(f0.x), h1 = bf_hi_f(f0.y), h2 = bf_hi_f(f0.z), h3 = bf_hi_f(f0.w);
        float h4 = bf_hi_f(f1.x), h5 = bf_hi_f(f1.y), h6 = bf_hi_f(f1.z), h7 = bf_hi_f(f1.w);
        uint4 hv = make_uint4(pack2bf(h0, h1), pack2bf(h2, h3), pack2bf(h4, h5), pack2bf(h6, h7));
        uint4 lv = make_uint4(pack2bf(f0.x - h0, f0.y - h1), pack2bf(f0.z - h2, f0.w - h3),
                              pack2bf(f1.x - h4, f1.y - h5), pack2bf(f1.z - h6, f1.w - h7));
        *(uint4*)&sm2[G2_AH + r * G2_LDA + k8] = hv;
        *(uint4*)&sm2[G2_AL + r * G2_LDA + k8] = lv;
    }
    // stage B: 256 n x 64 k
#pragma unroll
    for (int i = 0; i < 8; i++) {
        int c = tid + i * 256;
        int n = c >> 3, k8 = (c & 7) * 8;
        *(uint4*)&sm2[G2_BH + n * G2_LDA + k8] = *(const uint4*)&g_w2t_hi[n * 64 + k8];
        *(uint4*)&sm2[G2_BL + n * G2_LDA + k8] = *(const uint4*)&g_w2t_lo[n * 64 + k8];
    }
    __syncthreads();

    float acc[16][4];
#pragma unroll
    for (int i = 0; i < 16; i++)
#pragma unroll
        for (int j = 0; j < 4; j++) acc[i][j] = 0.0f;

#pragma unroll
    for (int ks = 0; ks < 4; ks++) {
        int col0 = ks * 16 + 2 * tig;
        int col1 = col0 + 8;
        int row0 = warpRow + g, row1 = row0 + 8;
        uint32_t ah[4], al[4];
        ah[0] = *(uint32_t*)&sm2[G2_AH + row0 * G2_LDA + col0];
        ah[1] = *(uint32_t*)&sm2[G2_AH + row1 * G2_LDA + col0];
        ah[2] = *(uint32_t*)&sm2[G2_AH + row0 * G2_LDA + col1];
        ah[3] = *(uint32_t*)&sm2[G2_AH + row1 * G2_LDA + col1];
        al[0] = *(uint32_t*)&sm2[G2_AL + row0 * G2_LDA + col0];
        al[1] = *(uint32_t*)&sm2[G2_AL + row1 * G2_LDA + col0];
        al[2] = *(uint32_t*)&sm2[G2_AL + row0 * G2_LDA + col1];
        al[3] = *(uint32_t*)&sm2[G2_AL + row1 * G2_LDA + col1];
#pragma unroll
        for (int nt = 0; nt < 16; nt++) {
            int nr = warpCol + nt * 8 + g;
            uint32_t bh[2], bl[2];
            bh[0] = *(uint32_t*)&sm2[G2_BH + nr * G2_LDA + col0];
            bh[1] = *(uint32_t*)&sm2[G2_BH + nr * G2_LDA + col1];
            bl[0] = *(uint32_t*)&sm2[G2_BL + nr * G2_LDA + col0];
            bl[1] = *(uint32_t*)&sm2[G2_BL + nr * G2_LDA + col1];
            mma16816(acc[nt], ah, bh);
            mma16816(acc[nt], ah, bl);
            mma16816(acc[nt], al, bh);
        }
    }
    int gr0 = rowBase + warpRow + g;
    int gr1 = gr0 + 8;
#pragma unroll
    for (int nt = 0; nt < 16; nt++) {
        int col = warpCol + nt * 8 + 2 * tig;
        float2 bv = *(const float2*)&bias[col];
        if (gr0 < M)
            *(float2*)&C[(size_t)gr0 * 256 + col] = make_float2(acc[nt][0] + bv.x, acc[nt][1] + bv.y);
        if (gr1 < M)
            *(float2*)&C[(size_t)gr1 * 256 + col] = make_float2(acc[nt][2] + bv.x, acc[nt][3] + bv.y);
    }
}

// ---------------------------------------------------------------------------
// CSR aggregation (warp per node, float2 per lane)
// ---------------------------------------------------------------------------
__global__ void k_agg64(const float* __restrict__ h,
                        const float* __restrict__ bias,
                        float* __restrict__ out, int n, int relu) {
    int node = blockIdx.x * 8 + (threadIdx.x >> 5);
    if (node >= n) return;
    int lane = threadIdx.x & 31;
    const float2* __restrict__ h2 = (const float2*)h;
    float dn = g_dinv[node];
    float2 self = h2[node * 32 + lane];
    float ax = self.x * dn * dn;
    float ay = self.y * dn * dn;
    int p = g_off[node], end = g_off[node + 1];
    for (; p + 1 < end; p += 2) {
        int s0 = g_esrc[p], s1 = g_esrc[p + 1];
        float w0 = g_dinv[s0] * dn, w1 = g_dinv[s1] * dn;
        float2 v0 = h2[s0 * 32 + lane];
        float2 v1 = h2[s1 * 32 + lane];
        ax += v0.x * w0 + v1.x * w1;
        ay += v0.y * w0 + v1.y * w1;
    }
    if (p < end) {
        int s = g_esrc[p];
        float w = g_dinv[s] * dn;
        float2 v = h2[s * 32 + lane];
        ax += v.x * w;
        ay += v.y * w;
    }
    if (bias) {
        float2 b = ((const float2*)bias)[lane];
        ax += b.x; ay += b.y;
    }
    if (relu) { ax = fmaxf(ax, 0.0f); ay = fmaxf(ay, 0.0f); }
    ((float2*)out)[node * 32 + lane] = make_float2(ax, ay);
}

// ---------------------------------------------------------------------------
// Fused mid: z, hd, pred
// ---------------------------------------------------------------------------
__global__ void k_fused_mid(const float* __restrict__ h1,
                            const float* __restrict__ Wef, const float* __restrict__ bef,
                            const float* __restrict__ Wdf, const float* __restrict__ bdf,
                            const float* __restrict__ Wc,  const float* __restrict__ bc,
                            float* __restrict__ z_out, float* __restrict__ hd_out,
                            float* __restrict__ pred_out, int n) {
    __shared__ float sWef[64 * 32];
    __shared__ float sWdf[32 * 64];
    __shared__ float sWc[32 * 3];
    __shared__ float sbef[32], sbdf[64], sbc[3];
    __shared__ float sh[16][64];
    __shared__ float sz[16][32];
    int tid = threadIdx.x;  // 256
    for (int i = tid; i < 64 * 32; i += 256) sWef[i] = Wef[i];
    for (int i = tid; i < 32 * 64; i += 256) sWdf[i] = Wdf[i];
    for (int i = tid; i < 32 * 3; i += 256) sWc[i] = Wc[i];
    if (tid < 32) sbef[tid] = bef[tid];
    if (tid < 64) sbdf[tid] = bdf[tid];
    if (tid < 3)  sbc[tid]  = bc[tid];
    int rowBase = blockIdx.x * 16;
    for (int i = tid; i < 16 * 64; i += 256) {
        int r = i >> 6, c = i & 63;
        int gr = rowBase + r;
        sh[r][c] = (gr < n) ? h1[gr * 64 + c] : 0.0f;
    }
    __syncthreads();
    for (int o = tid; o < 512; o += 256) {
        int r = o >> 5, j = o & 31;
        float acc = sbef[j];
#pragma unroll
        for (int k = 0; k < 64; k++) acc += sh[r][k] * sWef[k * 32 + j];
        sz[r][j] = acc;
        int gr = rowBase + r;
        if (gr < n) z_out[gr * 32 + j] = acc;
    }
    __syncthreads();
    for (int o = tid; o < 1024; o += 256) {
        int r = o >> 6, j = o & 63;
        float acc = sbdf[j];
#pragma unroll
        for (int k = 0; k < 32; k++) acc += sz[r][k] * sWdf[k * 64 + j];
        acc = fmaxf(acc, 0.0f);
        int gr = rowBase + r;
        if (gr < n) hd_out[gr * 64 + j] = acc;
    }
    for (int o = tid; o < 48; o += 256) {
        int r = o / 3, j = o % 3;
        float acc = sbc[j];
#pragma unroll
        for (int k = 0; k < 32; k++) acc += sz[r][k] * sWc[k * 3 + j];
        int gr = rowBase + r;
        if (gr < n) pred_out[gr * 3 + j] = acc;
    }
}

// ---------------------------------------------------------------------------
// Host launch
// ---------------------------------------------------------------------------
extern "C" void kernel_launch(void* const* d_in, const int* in_sizes, int n_in,
                              void* d_out, int out_size) {
    const float* x         = (const float*)d_in[0];
    const int*   edge_idx  = (const int*)d_in[1];
    const float* W_enc_gnn = (const float*)d_in[3];
    const float* b_enc_gnn = (const float*)d_in[4];
    const float* W_enc_fc  = (const float*)d_in[5];
    const float* b_enc_fc  = (const float*)d_in[6];
    const float* W_dec_fc  = (const float*)d_in[7];
    const float* b_dec_fc  = (const float*)d_in[8];
    const float* W_dec_gnn = (const float*)d_in[9];
    const float* b_dec_gnn = (const float*)d_in[10];
    const float* W_cond    = (const float*)d_in[11];
    const float* b_cond    = (const float*)d_in[12];

    int N = in_sizes[0] / 256;
    int E = in_sizes[2];
    const int* src = edge_idx;
    const int* dst = edge_idx + E;

    float* out_xrecon = (float*)d_out;
    float* out_z      = out_xrecon + (size_t)N * 256;
    float* out_pred   = out_z + (size_t)N * 32;

    float *p_h1pre, *p_h1, *p_hd, *p_a2;
    int *p_cnt;
    cudaGetSymbolAddress((void**)&p_h1pre, g_h1pre);
    cudaGetSymbolAddress((void**)&p_h1,    g_h1);
    cudaGetSymbolAddress((void**)&p_hd,    g_hd);
    cudaGetSymbolAddress((void**)&p_a2,    g_a2);
    cudaGetSymbolAddress((void**)&p_cnt,   g_cnt);

    cudaFuncSetAttribute(k_mma_gemm1, cudaFuncAttributeMaxDynamicSharedMemorySize, G1_SMEM);
    cudaFuncSetAttribute(k_mma_gemm2, cudaFuncAttributeMaxDynamicSharedMemorySize, G2_SMEM);

    int nbE  = (E + 255) / 256;
    int nbSc = (N + 1023) / 1024;

    cudaMemsetAsync(p_cnt, 0, (size_t)N * sizeof(int), 0);
    k_wconv<<<128, 256>>>(W_enc_gnn, W_dec_gnn);
    k_count<<<nbE, 256>>>(dst, E);
    k_scan_bsum<<<nbSc, 1024>>>(N);
    k_scan_sums<<<1, 1024>>>(nbSc);
    k_scan_final<<<nbSc, 1024>>>(N, E);
    k_fill<<<nbE, 256>>>(src, dst, E);

    k_mma_gemm1<<<(N + 127) / 128, 256, G1_SMEM>>>(x, p_h1pre, N);
    k_agg64<<<(N + 7) / 8, 256>>>(p_h1pre, b_enc_gnn, p_h1, N, 1);

    k_fused_mid<<<(N + 15) / 16, 256>>>(p_h1, W_enc_fc, b_enc_fc,
                                        W_dec_fc, b_dec_fc, W_cond, b_cond,
                                        out_z, p_hd, out_pred, N);

    k_agg64<<<(N + 7) / 8, 256>>>(p_hd, (const float*)nullptr, p_a2, N, 0);
    k_mma_gemm2<<<(N + 63) / 64, 256, G2_SMEM>>>(p_a2, b_dec_gnn, out_xrecon, N);
}